// round 14
// baseline (speedup 1.0000x reference)
#include <cuda_runtime.h>
#include <cuda_fp16.h>
#include <cstdint>

typedef __half h16;

// Problem constants
#define HID   4096
#define TT    2048     // B*S tokens
#define SEQ   1024
#define BSZ   2
#define NH    32
#define NKV   8
#define HD    128
#define DKV   (NKV * HD)
#define NQKV  (HID + 2 * DKV)   // 6144 fused output columns

// ---------------- device-global scratch (no runtime allocation allowed) ----------------
__device__ __align__(128) h16   g_Xh[(size_t)TT * HID];
__device__ __align__(128) h16   g_Wqkv[(size_t)NQKV * HID];   // rows: 0..4095 Q, 4096..5119 K, 5120..6143 V
__device__ __align__(128) h16   g_Wo[(size_t)HID * HID];
__device__ __align__(128) float g_Sqkv[NQKV];
__device__ __align__(128) float g_Bqkv[NQKV];
__device__ __align__(128) h16   g_Q[(size_t)BSZ * NH * SEQ * HD];
__device__ __align__(128) h16   g_K[(size_t)BSZ * NKV * SEQ * HD];
__device__ __align__(128) h16   g_V[(size_t)BSZ * NKV * SEQ * HD];
__device__ __align__(128) h16   g_AO[(size_t)TT * HID];

// ---------------- helpers ----------------
__device__ __forceinline__ void cp16(void* s, const void* g) {
    unsigned sa = (unsigned)__cvta_generic_to_shared(s);
    asm volatile("cp.async.cg.shared.global [%0], [%1], 16;" ::"r"(sa), "l"(g));
}
__device__ __forceinline__ void cp_commit() { asm volatile("cp.async.commit_group;"); }
template <int N>
__device__ __forceinline__ void cp_waitg() { asm volatile("cp.async.wait_group %0;" ::"n"(N)); }

__device__ __forceinline__ void ldsm4(unsigned addr, unsigned (&r)[4]) {
    asm volatile("ldmatrix.sync.aligned.m8n8.x4.shared.b16 {%0,%1,%2,%3}, [%4];"
                 : "=r"(r[0]), "=r"(r[1]), "=r"(r[2]), "=r"(r[3]) : "r"(addr));
}
__device__ __forceinline__ void ldsm4t(unsigned addr, unsigned (&r)[4]) {
    asm volatile("ldmatrix.sync.aligned.m8n8.x4.trans.shared.b16 {%0,%1,%2,%3}, [%4];"
                 : "=r"(r[0]), "=r"(r[1]), "=r"(r[2]), "=r"(r[3]) : "r"(addr));
}
__device__ __forceinline__ void mma_f16(float (&c)[4], const unsigned (&a)[4], const unsigned* b) {
    asm volatile(
        "mma.sync.aligned.m16n8k16.row.col.f32.f16.f16.f32 "
        "{%0,%1,%2,%3}, {%4,%5,%6,%7}, {%8,%9}, {%0,%1,%2,%3};\n"
        : "+f"(c[0]), "+f"(c[1]), "+f"(c[2]), "+f"(c[3])
        : "r"(a[0]), "r"(a[1]), "r"(a[2]), "r"(a[3]), "r"(b[0]), "r"(b[1]));
}
__device__ __forceinline__ unsigned packh2(float a, float b) {
    __half2 t = __floats2half2_rn(a, b);
    return *reinterpret_cast<unsigned*>(&t);
}
__device__ __forceinline__ unsigned ex2h2(float a, float b) {
    __half2 t = __floats2half2_rn(a, b);
    unsigned x = *reinterpret_cast<unsigned*>(&t), p;
    asm("ex2.approx.f16x2 %0, %1;" : "=r"(p) : "r"(x));
    return p;
}
__device__ __forceinline__ float2 h2f2(unsigned p) {
    return __half22float2(*reinterpret_cast<__half2*>(&p));
}

// ---------------- single fused conversion kernel ----------------
#define U_WQ  (HID * HID / 8)        // 2097152
#define U_WKV (DKV * HID / 8)        // 524288
#define U_XH  (TT * HID / 8)         // 1048576
#define U0 U_WQ
#define U1 (U0 + U_WKV)
#define U2 (U1 + U_WKV)
#define U3 (U2 + U_WQ)
#define U4 (U3 + U_XH)
#define U_SC 768
#define U_TOT (U4 + U_SC)

__device__ __forceinline__ void conv_i8(const int* __restrict__ src, h16* __restrict__ dst, int u) {
    const int4* wp = (const int4*)src + (size_t)u * 2;
    int4 a = wp[0], b = wp[1];
    uint4 o;
    o.x = packh2((float)a.x, (float)a.y);
    o.y = packh2((float)a.z, (float)a.w);
    o.z = packh2((float)b.x, (float)b.y);
    o.w = packh2((float)b.z, (float)b.w);
    ((uint4*)dst)[u] = o;
}
__global__ void convert_all_kernel(
    const int* __restrict__ wq, const int* __restrict__ wk,
    const int* __restrict__ wv, const int* __restrict__ wo,
    const float* __restrict__ hidden,
    const float* __restrict__ qs, const float* __restrict__ bq,
    const float* __restrict__ ks, const float* __restrict__ bk,
    const float* __restrict__ vs,
    h16* __restrict__ Wqkv, h16* __restrict__ Wo, h16* __restrict__ Xh,
    float* __restrict__ S, float* __restrict__ B) {
    int i = blockIdx.x * blockDim.x + threadIdx.x;
    if (i < U0) {
        conv_i8(wq, Wqkv, i);
    } else if (i < U1) {
        conv_i8(wk, Wqkv + (size_t)HID * HID, i - U0);
    } else if (i < U2) {
        conv_i8(wv, Wqkv + (size_t)(HID + DKV) * HID, i - U1);
    } else if (i < U3) {
        conv_i8(wo, Wo, i - U2);
    } else if (i < U4) {
        int u = i - U3;
        const float4* xp = (const float4*)hidden + (size_t)u * 2;
        float4 a = xp[0], b = xp[1];
        uint4 o;
        o.x = packh2(a.x, a.y);
        o.y = packh2(a.z, a.w);
        o.z = packh2(b.x, b.y);
        o.w = packh2(b.z, b.w);
        ((uint4*)Xh)[u] = o;
    } else if (i < U_TOT) {
        int c0 = (i - U4) * 8;
#pragma unroll
        for (int k = 0; k < 8; k++) {
            int c = c0 + k;
            if (c < HID)            { S[c] = qs[c];             B[c] = bq[c]; }
            else if (c < HID + DKV) { S[c] = ks[c - HID];       B[c] = bk[c - HID]; }
            else                    { S[c] = vs[c - HID - DKV]; B[c] = 0.f; }
        }
    }
}

// ---------------- fp16 GEMM: C[M,N] = A[M,K=4096] * W[N,K]^T ----------------
// 128x128 CTA tile, BK=64, 3-stage cp.async pipeline, occupancy 2,
// explicit fragment double-buffering (LSU/tensor overlap).
#define BKT 64
#define KST 72
#define GROWS 256
#define STG_E (GROWS * KST)       // 18432 elements per stage
#define GEMM_SMEM (3 * STG_E * 2) // 110592 bytes

__global__ __launch_bounds__(256, 2) void gemm_f16(
    const h16* __restrict__ A, const h16* __restrict__ W,
    const float* __restrict__ scale, const float* __restrict__ bias,
    int N, int mode,
    float* __restrict__ outF,
    h16* __restrict__ Qp, h16* __restrict__ Kp, h16* __restrict__ Vp) {
    extern __shared__ h16 sm[];
    const int tid = threadIdx.x, lane = tid & 31, wid = tid >> 5;
    const int mBase = blockIdx.y * 128, nBase = blockIdx.x * 128;
    const int wm = (wid & 3) * 32, wn = (wid >> 2) * 64;
    const unsigned sbase = (unsigned)__cvta_generic_to_shared(sm);

    // per-warp ldsm base offsets (ks-invariant parts)
    const unsigned aRow0 = (unsigned)((wm + (lane & 15)) * KST + (lane >> 4) * 8) * 2;
    const unsigned aRow1 = aRow0 + (unsigned)(16 * KST) * 2;
    const unsigned bCol = (unsigned)(((lane >> 3) & 1) * 8) * 2;
    unsigned bRow[4];
#pragma unroll
    for (int ni = 0; ni < 4; ni++)
        bRow[ni] = (unsigned)((wn + ni * 16 + (lane & 7) + ((lane >> 4) << 3)) * KST) * 2 + bCol;

    float acc[2][8][4];
#pragma unroll
    for (int mi = 0; mi < 2; mi++)
#pragma unroll
        for (int nf = 0; nf < 8; nf++)
#pragma unroll
            for (int e = 0; e < 4; e++) acc[mi][nf][e] = 0.f;

    auto loadStage = [&](int st, int k0) {
        h16* s = sm + st * STG_E;
#pragma unroll
        for (int i = 0; i < 8; i++) {
            int idx = tid + i * 256;
            int row = idx >> 3, q = idx & 7;
            const h16* src = (row < 128)
                                 ? A + (size_t)(mBase + row) * HID + k0 + q * 8
                                 : W + (size_t)(nBase + row - 128) * HID + k0 + q * 8;
            cp16(s + row * KST + q * 8, src);
        }
    };

    loadStage(0, 0); cp_commit();
    loadStage(1, BKT); cp_commit();

    unsigned aF[2][2][4], bF[2][4][4];

    const int KT = HID / BKT;  // 64
    for (int kt = 0; kt < KT; kt++) {
        if (kt + 1 < KT) cp_waitg<1>(); else cp_waitg<0>();
        __syncthreads();
        if (kt + 2 < KT) { loadStage((kt + 2) % 3, (kt + 2) * BKT); cp_commit(); }

        const int st = kt % 3;
        const unsigned ab = sbase + (unsigned)(st * STG_E) * 2;
        const unsigned bb = ab + (unsigned)(128 * KST) * 2;

        // prime fragments for ks=0
        {
            const unsigned kofs = 0;
            ldsm4(ab + aRow0 + kofs, aF[0][0]);
            ldsm4(ab + aRow1 + kofs, aF[0][1]);
#pragma unroll
            for (int ni = 0; ni < 4; ni++) ldsm4(bb + bRow[ni] + kofs, bF[0][ni]);
        }
#pragma unroll
        for (int ks = 0; ks < 4; ks++) {
            const int cur = ks & 1, nxt = cur ^ 1;
            if (ks < 3) {
                const unsigned kofs = (unsigned)((ks + 1) * 16) * 2;
                ldsm4(ab + aRow0 + kofs, aF[nxt][0]);
                ldsm4(ab + aRow1 + kofs, aF[nxt][1]);
#pragma unroll
                for (int ni = 0; ni < 4; ni++) ldsm4(bb + bRow[ni] + kofs, bF[nxt][ni]);
            }
#pragma unroll
            for (int mi = 0; mi < 2; mi++)
#pragma unroll
                for (int ni = 0; ni < 4; ni++) {
                    mma_f16(acc[mi][2 * ni],     aF[cur][mi], &bF[cur][ni][0]);
                    mma_f16(acc[mi][2 * ni + 1], aF[cur][mi], &bF[cur][ni][2]);
                }
        }
    }

    // ---- epilogue: paired stores (adjacent columns)
#pragma unroll
    for (int mi = 0; mi < 2; mi++)
#pragma unroll
        for (int nf = 0; nf < 8; nf++)
#pragma unroll
            for (int p = 0; p < 2; p++) {
                const int r = mBase + wm + mi * 16 + (lane >> 2) + p * 8;
                const int c = nBase + wn + nf * 8 + 2 * (lane & 3);
                float va = acc[mi][nf][2 * p]     * scale[c];
                float vb = acc[mi][nf][2 * p + 1] * scale[c + 1];
                if (bias) { va += bias[c]; vb += bias[c + 1]; }
                if (mode == 0) {
                    *reinterpret_cast<float2*>(outF + (size_t)r * N + c) = make_float2(va, vb);
                } else {
                    h16* dst; int nh, cb;
                    if (c < HID)            { dst = Qp; nh = NH;  cb = c; }
                    else if (c < HID + DKV) { dst = Kp; nh = NKV; cb = c - HID; }
                    else                    { dst = Vp; nh = NKV; cb = c - HID - DKV; }
                    const int head = cb >> 7, d = cb & 127;
                    const int bb2 = r >> 10, ss = r & 1023;
                    const size_t idx = (((size_t)(bb2 * nh + head)) * SEQ + ss) * HD + d;
                    *reinterpret_cast<unsigned*>(dst + idx) = packh2(va, vb);
                }
            }
}

// ---------------- flash attention (causal, GQA), single-term fp16 ----------------
#define QST 136
#define ASTG_E (128 * QST)            // 34816 B per stage
#define ATTN_SMEM (3 * ASTG_E * 2)    // 104448 bytes

__global__ __launch_bounds__(256) void attn_kernel(
    const h16* __restrict__ Q, const h16* __restrict__ K, const h16* __restrict__ V,
    h16* __restrict__ AO) {
    extern __shared__ h16 sm[];
    const int tid = threadIdx.x, lane = tid & 31, wid = tid >> 5;
    const int qi = (int)gridDim.x - 1 - (int)blockIdx.x;  // heavy tiles first
    const int h = blockIdx.y, b = blockIdx.z;
    const int kvh = h >> 2;  // GROUPS = 4
    const unsigned sbase = (unsigned)__cvta_generic_to_shared(sm);
    const float SCLG = 0.08838834764831845f * 1.4426950408889634f;
    const int wm = wid * 16;

    const size_t qoff = (((size_t)(b * NH + h)) * SEQ + qi * 128) * HD;
    {
#pragma unroll
        for (int i = 0; i < 8; i++) {
            int c = tid + i * 256;
            int row = c >> 4, cb = (c & 15) * 8;
            cp16(sm + row * QST + cb, Q + qoff + row * HD + cb);
        }
        cp_commit();
        cp_waitg<0>();
        __syncthreads();
    }
    unsigned qf[8][4];
#pragma unroll
    for (int ks = 0; ks < 8; ks++) {
        int row = wm + (lane & 15);
        int col = ks * 16 + (lane >> 4) * 8;
        ldsm4(sbase + (unsigned)(row * QST + col) * 2, qf[ks]);
    }
    __syncthreads();

    const size_t kvbase = ((size_t)(b * NKV + kvh)) * SEQ * HD;
    auto loadKV = [&](int slot, int j) {
        h16* s = sm + slot * ASTG_E;
        const size_t koff = kvbase + (size_t)(j * 64) * HD;
#pragma unroll
        for (int i = 0; i < 8; i++) {
            int idx = tid + i * 256;
            int r = idx >> 4, q = (idx & 15) * 8;
            const h16* src = (r < 64) ? K + koff + (size_t)r * HD + q
                                      : V + koff + (size_t)(r - 64) * HD + q;
            cp16(s + r * QST + q, src);
        }
    };

    float o[16][4];
#pragma unroll
    for (int nf = 0; nf < 16; nf++)
#pragma unroll
        for (int e = 0; e < 4; e++) o[nf][e] = 0.f;
    float m0 = -1e30f, m1 = -1e30f, l0 = 0.f, l1 = 0.f;

    const int jn = 2 * qi + 2;
    loadKV(0, 0); cp_commit();
    if (jn > 1) { loadKV(1, 1); cp_commit(); }

    for (int j = 0; j < jn; j++) {
        if (j + 1 < jn) cp_waitg<1>(); else cp_waitg<0>();
        __syncthreads();
        if (j + 2 < jn) { loadKV((j + 2) % 3, j + 2); cp_commit(); }

        const unsigned sb = sbase + (unsigned)((j % 3) * ASTG_E) * 2;
        const unsigned khb = sb;
        const unsigned vhb = sb + (unsigned)(64 * QST) * 2;

        float s4[8][4];
#pragma unroll
        for (int nf = 0; nf < 8; nf++)
#pragma unroll
            for (int e = 0; e < 4; e++) s4[nf][e] = 0.f;
#pragma unroll
        for (int ks = 0; ks < 8; ks++) {
            unsigned kf[4][4];
#pragma unroll
            for (int ni = 0; ni < 4; ni++) {
                int row = ni * 16 + (lane & 7) + ((lane >> 4) << 3);
                int col = ks * 16 + ((lane >> 3) & 1) * 8;
                ldsm4(khb + (unsigned)(row * QST + col) * 2, kf[ni]);
            }
#pragma unroll
            for (int ni = 0; ni < 4; ni++) {
                mma_f16(s4[2 * ni],     qf[ks], &kf[ni][0]);
                mma_f16(s4[2 * ni + 1], qf[ks], &kf[ni][2]);
            }
        }

        const int rbase = qi * 128 + wm + (lane >> 2);
        const bool needMask = (j >= 2 * qi);
#pragma unroll
        for (int nf = 0; nf < 8; nf++)
#pragma unroll
            for (int e = 0; e < 4; e++) {
                s4[nf][e] *= SCLG;
                if (needMask) {
                    int r = rbase + ((e >> 1) << 3);
                    int cg = j * 64 + nf * 8 + 2 * (lane & 3) + (e & 1);
                    if (cg > r) s4[nf][e] = -1e30f;
                }
            }

        float mx0 = -1e30f, mx1 = -1e30f;
#pragma unroll
        for (int nf = 0; nf < 8; nf++) {
            mx0 = fmaxf(mx0, fmaxf(s4[nf][0], s4[nf][1]));
            mx1 = fmaxf(mx1, fmaxf(s4[nf][2], s4[nf][3]));
        }
        mx0 = fmaxf(mx0, __shfl_xor_sync(0xffffffffu, mx0, 1));
        mx0 = fmaxf(mx0, __shfl_xor_sync(0xffffffffu, mx0, 2));
        mx1 = fmaxf(mx1, __shfl_xor_sync(0xffffffffu, mx1, 1));
        mx1 = fmaxf(mx1, __shfl_xor_sync(0xffffffffu, mx1, 2));
        float mn0 = fmaxf(m0, mx0), mn1 = fmaxf(m1, mx1);
        float c0 = exp2f(m0 - mn0), c1 = exp2f(m1 - mn1);
        m0 = mn0;
        m1 = mn1;

        float rs0 = 0.f, rs1 = 0.f;
        unsigned pfrag[4][4];
#pragma unroll
        for (int nf = 0; nf < 8; nf++) {
            unsigned pa = ex2h2(s4[nf][0] - mn0, s4[nf][1] - mn0);
            unsigned pb = ex2h2(s4[nf][2] - mn1, s4[nf][3] - mn1);
            float2 fa = h2f2(pa), fb = h2f2(pb);
            rs0 += fa.x + fa.y;
            rs1 += fb.x + fb.y;
            int kc = nf >> 1, sub = nf & 1;
            pfrag[kc][2 * sub] = pa;
            pfrag[kc][2 * sub + 1] = pb;
        }
        rs0 += __shfl_xor_sync(0xffffffffu, rs0, 1);
        rs0 += __shfl_xor_sync(0xffffffffu, rs0, 2);
        rs1 += __shfl_xor_sync(0xffffffffu, rs1, 1);
        rs1 += __shfl_xor_sync(0xffffffffu, rs1, 2);
        l0 = l0 * c0 + rs0;
        l1 = l1 * c1 + rs1;
#pragma unroll
        for (int nf = 0; nf < 16; nf++) {
            o[nf][0] *= c0;
            o[nf][1] *= c0;
            o[nf][2] *= c1;
            o[nf][3] *= c1;
        }

#pragma unroll
        for (int kc = 0; kc < 4; kc++) {
#pragma unroll
            for (int dg = 0; dg < 8; dg++) {
                int row = kc * 16 + (lane & 15);
                int col = dg * 16 + (lane >> 4) * 8;
                unsigned vf[4];
                ldsm4t(vhb + (unsigned)(row * QST + col) * 2, vf);
                mma_f16(o[2 * dg],     pfrag[kc], &vf[0]);
                mma_f16(o[2 * dg + 1], pfrag[kc], &vf[2]);
            }
        }
    }

    float inv0 = 1.f / l0, inv1 = 1.f / l1;
    const int tok0 = b * SEQ + qi * 128 + wm + (lane >> 2);
#pragma unroll
    for (int nf = 0; nf < 16; nf++)
#pragma unroll
        for (int p = 0; p < 2; p++) {
            int r = tok0 + p * 8;
            int d = nf * 8 + 2 * (lane & 3);
            float va = o[nf][2 * p] * ((p == 0) ? inv0 : inv1);
            float vb = o[nf][2 * p + 1] * ((p == 0) ? inv0 : inv1);
            *reinterpret_cast<unsigned*>(AO + (size_t)r * HID + h * HD + d) = packh2(va, vb);
        }
}

// ---------------- host launch ----------------
extern "C" void kernel_launch(void* const* d_in, const int* in_sizes, int n_in,
                              void* d_out, int out_size) {
    (void)in_sizes; (void)n_in; (void)out_size;
    const float* hidden = (const float*)d_in[0];
    const int*   wq   = (const int*)d_in[2];
    const float* wq_s = (const float*)d_in[3];
    const float* bq   = (const float*)d_in[4];
    const int*   wk   = (const int*)d_in[5];
    const float* wk_s = (const float*)d_in[6];
    const float* bk   = (const float*)d_in[7];
    const int*   wv   = (const int*)d_in[8];
    const float* wv_s = (const float*)d_in[9];
    const int*   wo   = (const int*)d_in[10];
    const float* wo_s = (const float*)d_in[11];
    float* out = (float*)d_out;

    h16 *Xh, *Wqkv, *Wo, *Q, *K, *V, *AO;
    float *Sq, *Bq;
    cudaGetSymbolAddress((void**)&Xh,   g_Xh);
    cudaGetSymbolAddress((void**)&Wqkv, g_Wqkv);
    cudaGetSymbolAddress((void**)&Wo,   g_Wo);
    cudaGetSymbolAddress((void**)&Sq,   g_Sqkv);
    cudaGetSymbolAddress((void**)&Bq,   g_Bqkv);
    cudaGetSymbolAddress((void**)&Q,    g_Q);
    cudaGetSymbolAddress((void**)&K,    g_K);
    cudaGetSymbolAddress((void**)&V,    g_V);
    cudaGetSymbolAddress((void**)&AO,   g_AO);

    cudaFuncSetAttribute(gemm_f16, cudaFuncAttributeMaxDynamicSharedMemorySize, GEMM_SMEM);
    cudaFuncSetAttribute(attn_kernel, cudaFuncAttributeMaxDynamicSharedMemorySize, ATTN_SMEM);

    // ONE fused conversion kernel
    convert_all_kernel<<<(U_TOT + 255) / 256, 256>>>(
        wq, wk, wv, wo, hidden, wq_s, bq, wk_s, bk, wv_s, Wqkv, Wo, Xh, Sq, Bq);

    // fused QKV projection (single GEMM over N=6144)
    gemm_f16<<<dim3(NQKV / 128, TT / 128), 256, GEMM_SMEM>>>(
        Xh, Wqkv, Sq, Bq, NQKV, 1, nullptr, Q, K, V);

    // causal GQA flash attention -> fp16 AO (token-major)
    attn_kernel<<<dim3(SEQ / 128, NH, BSZ), 256, ATTN_SMEM>>>(Q, K, V, AO);

    // output projection -> fp32 d_out
    gemm_f16<<<dim3(HID / 128, TT / 128), 256, GEMM_SMEM>>>(
        AO, Wo, wo_s, nullptr, HID, 0, out, nullptr, nullptr, nullptr);
}

// round 15
// speedup vs baseline: 1.1092x; 1.1092x over previous
#include <cuda_runtime.h>
#include <cuda_fp16.h>
#include <cstdint>

typedef __half h16;

// Problem constants
#define HID   4096
#define TT    2048     // B*S tokens
#define SEQ   1024
#define BSZ   2
#define NH    32
#define NKV   8
#define HD    128
#define DKV   (NKV * HD)
#define NQKV  (HID + 2 * DKV)   // 6144 fused output columns

// ---------------- device-global scratch (no runtime allocation allowed) ----------------
__device__ __align__(128) h16   g_Xh[(size_t)TT * HID];
__device__ __align__(128) h16   g_Wqkv[(size_t)NQKV * HID];   // rows: 0..4095 Q, 4096..5119 K, 5120..6143 V
__device__ __align__(128) h16   g_Wo[(size_t)HID * HID];
__device__ __align__(128) float g_Sqkv[NQKV];
__device__ __align__(128) float g_Bqkv[NQKV];
__device__ __align__(128) h16   g_Q[(size_t)BSZ * NH * SEQ * HD];
__device__ __align__(128) h16   g_K[(size_t)BSZ * NKV * SEQ * HD];
__device__ __align__(128) h16   g_V[(size_t)BSZ * NKV * SEQ * HD];
__device__ __align__(128) h16   g_AO[(size_t)TT * HID];

// ---------------- helpers ----------------
__device__ __forceinline__ void cp16(void* s, const void* g) {
    unsigned sa = (unsigned)__cvta_generic_to_shared(s);
    asm volatile("cp.async.cg.shared.global [%0], [%1], 16;" ::"r"(sa), "l"(g));
}
__device__ __forceinline__ void cp_commit() { asm volatile("cp.async.commit_group;"); }
template <int N>
__device__ __forceinline__ void cp_waitg() { asm volatile("cp.async.wait_group %0;" ::"n"(N)); }

__device__ __forceinline__ void ldsm4(unsigned addr, unsigned (&r)[4]) {
    asm volatile("ldmatrix.sync.aligned.m8n8.x4.shared.b16 {%0,%1,%2,%3}, [%4];"
                 : "=r"(r[0]), "=r"(r[1]), "=r"(r[2]), "=r"(r[3]) : "r"(addr));
}
__device__ __forceinline__ void ldsm4t(unsigned addr, unsigned (&r)[4]) {
    asm volatile("ldmatrix.sync.aligned.m8n8.x4.trans.shared.b16 {%0,%1,%2,%3}, [%4];"
                 : "=r"(r[0]), "=r"(r[1]), "=r"(r[2]), "=r"(r[3]) : "r"(addr));
}
__device__ __forceinline__ void mma_f16(float (&c)[4], const unsigned (&a)[4], const unsigned* b) {
    asm volatile(
        "mma.sync.aligned.m16n8k16.row.col.f32.f16.f16.f32 "
        "{%0,%1,%2,%3}, {%4,%5,%6,%7}, {%8,%9}, {%0,%1,%2,%3};\n"
        : "+f"(c[0]), "+f"(c[1]), "+f"(c[2]), "+f"(c[3])
        : "r"(a[0]), "r"(a[1]), "r"(a[2]), "r"(a[3]), "r"(b[0]), "r"(b[1]));
}
__device__ __forceinline__ unsigned packh2(float a, float b) {
    __half2 t = __floats2half2_rn(a, b);
    return *reinterpret_cast<unsigned*>(&t);
}
__device__ __forceinline__ unsigned ex2h2(float a, float b) {
    __half2 t = __floats2half2_rn(a, b);
    unsigned x = *reinterpret_cast<unsigned*>(&t), p;
    asm("ex2.approx.f16x2 %0, %1;" : "=r"(p) : "r"(x));
    return p;
}
__device__ __forceinline__ float2 h2f2(unsigned p) {
    return __half22float2(*reinterpret_cast<__half2*>(&p));
}

// ---------------- single fused conversion kernel ----------------
#define U_WQ  (HID * HID / 8)        // 2097152
#define U_WKV (DKV * HID / 8)        // 524288
#define U_XH  (TT * HID / 8)         // 1048576
#define U0 U_WQ
#define U1 (U0 + U_WKV)
#define U2 (U1 + U_WKV)
#define U3 (U2 + U_WQ)
#define U4 (U3 + U_XH)
#define U_SC 768
#define U_TOT (U4 + U_SC)

__device__ __forceinline__ void conv_i8(const int* __restrict__ src, h16* __restrict__ dst, int u) {
    const int4* wp = (const int4*)src + (size_t)u * 2;
    int4 a = wp[0], b = wp[1];
    uint4 o;
    o.x = packh2((float)a.x, (float)a.y);
    o.y = packh2((float)a.z, (float)a.w);
    o.z = packh2((float)b.x, (float)b.y);
    o.w = packh2((float)b.z, (float)b.w);
    ((uint4*)dst)[u] = o;
}
__global__ void convert_all_kernel(
    const int* __restrict__ wq, const int* __restrict__ wk,
    const int* __restrict__ wv, const int* __restrict__ wo,
    const float* __restrict__ hidden,
    const float* __restrict__ qs, const float* __restrict__ bq,
    const float* __restrict__ ks, const float* __restrict__ bk,
    const float* __restrict__ vs,
    h16* __restrict__ Wqkv, h16* __restrict__ Wo, h16* __restrict__ Xh,
    float* __restrict__ S, float* __restrict__ B) {
    int i = blockIdx.x * blockDim.x + threadIdx.x;
    if (i < U0) {
        conv_i8(wq, Wqkv, i);
    } else if (i < U1) {
        conv_i8(wk, Wqkv + (size_t)HID * HID, i - U0);
    } else if (i < U2) {
        conv_i8(wv, Wqkv + (size_t)(HID + DKV) * HID, i - U1);
    } else if (i < U3) {
        conv_i8(wo, Wo, i - U2);
    } else if (i < U4) {
        int u = i - U3;
        const float4* xp = (const float4*)hidden + (size_t)u * 2;
        float4 a = xp[0], b = xp[1];
        uint4 o;
        o.x = packh2(a.x, a.y);
        o.y = packh2(a.z, a.w);
        o.z = packh2(b.x, b.y);
        o.w = packh2(b.z, b.w);
        ((uint4*)Xh)[u] = o;
    } else if (i < U_TOT) {
        int c0 = (i - U4) * 8;
#pragma unroll
        for (int k = 0; k < 8; k++) {
            int c = c0 + k;
            if (c < HID)            { S[c] = qs[c];             B[c] = bq[c]; }
            else if (c < HID + DKV) { S[c] = ks[c - HID];       B[c] = bk[c - HID]; }
            else                    { S[c] = vs[c - HID - DKV]; B[c] = 0.f; }
        }
    }
}

// ---------------- fp16 GEMM: C[M,N] = A[M,K=4096] * W[N,K]^T ----------------
// 128x128 CTA tile, BK=64, 3-stage cp.async pipeline, occupancy 2.
// Prefetch cp.async is issued in 4 chunks interleaved with the ks compute steps
// to spread LSU pressure across the k-tile (single commit per k-tile).
#define BKT 64
#define KST 72
#define GROWS 256
#define STG_E (GROWS * KST)       // 18432 elements per stage
#define GEMM_SMEM (3 * STG_E * 2) // 110592 bytes

__global__ __launch_bounds__(256, 2) void gemm_f16(
    const h16* __restrict__ A, const h16* __restrict__ W,
    const float* __restrict__ scale, const float* __restrict__ bias,
    int N, int mode,
    float* __restrict__ outF,
    h16* __restrict__ Qp, h16* __restrict__ Kp, h16* __restrict__ Vp) {
    extern __shared__ h16 sm[];
    const int tid = threadIdx.x, lane = tid & 31, wid = tid >> 5;
    const int mBase = blockIdx.y * 128, nBase = blockIdx.x * 128;
    const int wm = (wid & 3) * 32, wn = (wid >> 2) * 64;
    const unsigned sbase = (unsigned)__cvta_generic_to_shared(sm);

    float acc[2][8][4];
#pragma unroll
    for (int mi = 0; mi < 2; mi++)
#pragma unroll
        for (int nf = 0; nf < 8; nf++)
#pragma unroll
            for (int e = 0; e < 4; e++) acc[mi][nf][e] = 0.f;

    auto loadChunk = [&](int st, int k0, int c) {
        h16* s = sm + st * STG_E;
#pragma unroll
        for (int i = 2 * c; i < 2 * c + 2; i++) {
            int idx = tid + i * 256;
            int row = idx >> 3, q = idx & 7;
            const h16* src = (row < 128)
                                 ? A + (size_t)(mBase + row) * HID + k0 + q * 8
                                 : W + (size_t)(nBase + row - 128) * HID + k0 + q * 8;
            cp16(s + row * KST + q * 8, src);
        }
    };
    auto loadStage = [&](int st, int k0) {
#pragma unroll
        for (int c = 0; c < 4; c++) loadChunk(st, k0, c);
    };

    loadStage(0, 0); cp_commit();
    loadStage(1, BKT); cp_commit();

    const int KT = HID / BKT;  // 64
    for (int kt = 0; kt < KT; kt++) {
        if (kt + 1 < KT) cp_waitg<1>(); else cp_waitg<0>();
        __syncthreads();

        const bool pf = (kt + 2 < KT);
        const int pst = (kt + 2) % 3;
        const int pk0 = (kt + 2) * BKT;

        const int st = kt % 3;
        const unsigned ab = sbase + (unsigned)(st * STG_E) * 2;
        const unsigned bb = ab + (unsigned)(128 * KST) * 2;
#pragma unroll
        for (int ks = 0; ks < 4; ks++) {
            if (pf) loadChunk(pst, pk0, ks);  // 2 cp16/thread, spread across ks
            int kc = ks * 16;
            unsigned aF[2][4], bF[4][4];
#pragma unroll
            for (int mi = 0; mi < 2; mi++) {
                int row = wm + mi * 16 + (lane & 15);
                int col = kc + (lane >> 4) * 8;
                ldsm4(ab + (unsigned)(row * KST + col) * 2, aF[mi]);
            }
#pragma unroll
            for (int ni = 0; ni < 4; ni++) {
                int row = wn + ni * 16 + (lane & 7) + ((lane >> 4) << 3);
                int col = kc + ((lane >> 3) & 1) * 8;
                ldsm4(bb + (unsigned)(row * KST + col) * 2, bF[ni]);
            }
#pragma unroll
            for (int mi = 0; mi < 2; mi++)
#pragma unroll
                for (int ni = 0; ni < 4; ni++) {
                    mma_f16(acc[mi][2 * ni],     aF[mi], &bF[ni][0]);
                    mma_f16(acc[mi][2 * ni + 1], aF[mi], &bF[ni][2]);
                }
        }
        if (pf) cp_commit();
    }

    // ---- epilogue: paired stores (adjacent columns)
#pragma unroll
    for (int mi = 0; mi < 2; mi++)
#pragma unroll
        for (int nf = 0; nf < 8; nf++)
#pragma unroll
            for (int p = 0; p < 2; p++) {
                const int r = mBase + wm + mi * 16 + (lane >> 2) + p * 8;
                const int c = nBase + wn + nf * 8 + 2 * (lane & 3);
                float va = acc[mi][nf][2 * p]     * scale[c];
                float vb = acc[mi][nf][2 * p + 1] * scale[c + 1];
                if (bias) { va += bias[c]; vb += bias[c + 1]; }
                if (mode == 0) {
                    *reinterpret_cast<float2*>(outF + (size_t)r * N + c) = make_float2(va, vb);
                } else {
                    h16* dst; int nh, cb;
                    if (c < HID)            { dst = Qp; nh = NH;  cb = c; }
                    else if (c < HID + DKV) { dst = Kp; nh = NKV; cb = c - HID; }
                    else                    { dst = Vp; nh = NKV; cb = c - HID - DKV; }
                    const int head = cb >> 7, d = cb & 127;
                    const int bb2 = r >> 10, ss = r & 1023;
                    const size_t idx = (((size_t)(bb2 * nh + head)) * SEQ + ss) * HD + d;
                    *reinterpret_cast<unsigned*>(dst + idx) = packh2(va, vb);
                }
            }
}

// ---------------- flash attention (causal, GQA), single-term fp16 ----------------
#define QST 136
#define ASTG_E (128 * QST)            // 34816 B per stage
#define ATTN_SMEM (3 * ASTG_E * 2)    // 104448 bytes

__global__ __launch_bounds__(256) void attn_kernel(
    const h16* __restrict__ Q, const h16* __restrict__ K, const h16* __restrict__ V,
    h16* __restrict__ AO) {
    extern __shared__ h16 sm[];
    const int tid = threadIdx.x, lane = tid & 31, wid = tid >> 5;
    const int qi = (int)gridDim.x - 1 - (int)blockIdx.x;  // heavy tiles first
    const int h = blockIdx.y, b = blockIdx.z;
    const int kvh = h >> 2;  // GROUPS = 4
    const unsigned sbase = (unsigned)__cvta_generic_to_shared(sm);
    const float SCLG = 0.08838834764831845f * 1.4426950408889634f;
    const int wm = wid * 16;

    const size_t qoff = (((size_t)(b * NH + h)) * SEQ + qi * 128) * HD;
    {
#pragma unroll
        for (int i = 0; i < 8; i++) {
            int c = tid + i * 256;
            int row = c >> 4, cb = (c & 15) * 8;
            cp16(sm + row * QST + cb, Q + qoff + row * HD + cb);
        }
        cp_commit();
        cp_waitg<0>();
        __syncthreads();
    }
    unsigned qf[8][4];
#pragma unroll
    for (int ks = 0; ks < 8; ks++) {
        int row = wm + (lane & 15);
        int col = ks * 16 + (lane >> 4) * 8;
        ldsm4(sbase + (unsigned)(row * QST + col) * 2, qf[ks]);
    }
    __syncthreads();

    const size_t kvbase = ((size_t)(b * NKV + kvh)) * SEQ * HD;
    auto loadKV = [&](int slot, int j) {
        h16* s = sm + slot * ASTG_E;
        const size_t koff = kvbase + (size_t)(j * 64) * HD;
#pragma unroll
        for (int i = 0; i < 8; i++) {
            int idx = tid + i * 256;
            int r = idx >> 4, q = (idx & 15) * 8;
            const h16* src = (r < 64) ? K + koff + (size_t)r * HD + q
                                      : V + koff + (size_t)(r - 64) * HD + q;
            cp16(s + r * QST + q, src);
        }
    };

    float o[16][4];
#pragma unroll
    for (int nf = 0; nf < 16; nf++)
#pragma unroll
        for (int e = 0; e < 4; e++) o[nf][e] = 0.f;
    float m0 = -1e30f, m1 = -1e30f, l0 = 0.f, l1 = 0.f;

    const int jn = 2 * qi + 2;
    loadKV(0, 0); cp_commit();
    if (jn > 1) { loadKV(1, 1); cp_commit(); }

    for (int j = 0; j < jn; j++) {
        if (j + 1 < jn) cp_waitg<1>(); else cp_waitg<0>();
        __syncthreads();
        if (j + 2 < jn) { loadKV((j + 2) % 3, j + 2); cp_commit(); }

        const unsigned sb = sbase + (unsigned)((j % 3) * ASTG_E) * 2;
        const unsigned khb = sb;
        const unsigned vhb = sb + (unsigned)(64 * QST) * 2;

        float s4[8][4];
#pragma unroll
        for (int nf = 0; nf < 8; nf++)
#pragma unroll
            for (int e = 0; e < 4; e++) s4[nf][e] = 0.f;
#pragma unroll
        for (int ks = 0; ks < 8; ks++) {
            unsigned kf[4][4];
#pragma unroll
            for (int ni = 0; ni < 4; ni++) {
                int row = ni * 16 + (lane & 7) + ((lane >> 4) << 3);
                int col = ks * 16 + ((lane >> 3) & 1) * 8;
                ldsm4(khb + (unsigned)(row * QST + col) * 2, kf[ni]);
            }
#pragma unroll
            for (int ni = 0; ni < 4; ni++) {
                mma_f16(s4[2 * ni],     qf[ks], &kf[ni][0]);
                mma_f16(s4[2 * ni + 1], qf[ks], &kf[ni][2]);
            }
        }

        const int rbase = qi * 128 + wm + (lane >> 2);
        const bool needMask = (j >= 2 * qi);
#pragma unroll
        for (int nf = 0; nf < 8; nf++)
#pragma unroll
            for (int e = 0; e < 4; e++) {
                s4[nf][e] *= SCLG;
                if (needMask) {
                    int r = rbase + ((e >> 1) << 3);
                    int cg = j * 64 + nf * 8 + 2 * (lane & 3) + (e & 1);
                    if (cg > r) s4[nf][e] = -1e30f;
                }
            }

        float mx0 = -1e30f, mx1 = -1e30f;
#pragma unroll
        for (int nf = 0; nf < 8; nf++) {
            mx0 = fmaxf(mx0, fmaxf(s4[nf][0], s4[nf][1]));
            mx1 = fmaxf(mx1, fmaxf(s4[nf][2], s4[nf][3]));
        }
        mx0 = fmaxf(mx0, __shfl_xor_sync(0xffffffffu, mx0, 1));
        mx0 = fmaxf(mx0, __shfl_xor_sync(0xffffffffu, mx0, 2));
        mx1 = fmaxf(mx1, __shfl_xor_sync(0xffffffffu, mx1, 1));
        mx1 = fmaxf(mx1, __shfl_xor_sync(0xffffffffu, mx1, 2));
        float mn0 = fmaxf(m0, mx0), mn1 = fmaxf(m1, mx1);
        float c0 = exp2f(m0 - mn0), c1 = exp2f(m1 - mn1);
        m0 = mn0;
        m1 = mn1;

        float rs0 = 0.f, rs1 = 0.f;
        unsigned pfrag[4][4];
#pragma unroll
        for (int nf = 0; nf < 8; nf++) {
            unsigned pa = ex2h2(s4[nf][0] - mn0, s4[nf][1] - mn0);
            unsigned pb = ex2h2(s4[nf][2] - mn1, s4[nf][3] - mn1);
            float2 fa = h2f2(pa), fb = h2f2(pb);
            rs0 += fa.x + fa.y;
            rs1 += fb.x + fb.y;
            int kc = nf >> 1, sub = nf & 1;
            pfrag[kc][2 * sub] = pa;
            pfrag[kc][2 * sub + 1] = pb;
        }
        rs0 += __shfl_xor_sync(0xffffffffu, rs0, 1);
        rs0 += __shfl_xor_sync(0xffffffffu, rs0, 2);
        rs1 += __shfl_xor_sync(0xffffffffu, rs1, 1);
        rs1 += __shfl_xor_sync(0xffffffffu, rs1, 2);
        l0 = l0 * c0 + rs0;
        l1 = l1 * c1 + rs1;
#pragma unroll
        for (int nf = 0; nf < 16; nf++) {
            o[nf][0] *= c0;
            o[nf][1] *= c0;
            o[nf][2] *= c1;
            o[nf][3] *= c1;
        }

#pragma unroll
        for (int kc = 0; kc < 4; kc++) {
#pragma unroll
            for (int dg = 0; dg < 8; dg++) {
                int row = kc * 16 + (lane & 15);
                int col = dg * 16 + (lane >> 4) * 8;
                unsigned vf[4];
                ldsm4t(vhb + (unsigned)(row * QST + col) * 2, vf);
                mma_f16(o[2 * dg],     pfrag[kc], &vf[0]);
                mma_f16(o[2 * dg + 1], pfrag[kc], &vf[2]);
            }
        }
    }

    float inv0 = 1.f / l0, inv1 = 1.f / l1;
    const int tok0 = b * SEQ + qi * 128 + wm + (lane >> 2);
#pragma unroll
    for (int nf = 0; nf < 16; nf++)
#pragma unroll
        for (int p = 0; p < 2; p++) {
            int r = tok0 + p * 8;
            int d = nf * 8 + 2 * (lane & 3);
            float va = o[nf][2 * p] * ((p == 0) ? inv0 : inv1);
            float vb = o[nf][2 * p + 1] * ((p == 0) ? inv0 : inv1);
            *reinterpret_cast<unsigned*>(AO + (size_t)r * HID + h * HD + d) = packh2(va, vb);
        }
}

// ---------------- host launch ----------------
extern "C" void kernel_launch(void* const* d_in, const int* in_sizes, int n_in,
                              void* d_out, int out_size) {
    (void)in_sizes; (void)n_in; (void)out_size;
    const float* hidden = (const float*)d_in[0];
    const int*   wq   = (const int*)d_in[2];
    const float* wq_s = (const float*)d_in[3];
    const float* bq   = (const float*)d_in[4];
    const int*   wk   = (const int*)d_in[5];
    const float* wk_s = (const float*)d_in[6];
    const float* bk   = (const float*)d_in[7];
    const int*   wv   = (const int*)d_in[8];
    const float* wv_s = (const float*)d_in[9];
    const int*   wo   = (const int*)d_in[10];
    const float* wo_s = (const float*)d_in[11];
    float* out = (float*)d_out;

    h16 *Xh, *Wqkv, *Wo, *Q, *K, *V, *AO;
    float *Sq, *Bq;
    cudaGetSymbolAddress((void**)&Xh,   g_Xh);
    cudaGetSymbolAddress((void**)&Wqkv, g_Wqkv);
    cudaGetSymbolAddress((void**)&Wo,   g_Wo);
    cudaGetSymbolAddress((void**)&Sq,   g_Sqkv);
    cudaGetSymbolAddress((void**)&Bq,   g_Bqkv);
    cudaGetSymbolAddress((void**)&Q,    g_Q);
    cudaGetSymbolAddress((void**)&K,    g_K);
    cudaGetSymbolAddress((void**)&V,    g_V);
    cudaGetSymbolAddress((void**)&AO,   g_AO);

    cudaFuncSetAttribute(gemm_f16, cudaFuncAttributeMaxDynamicSharedMemorySize, GEMM_SMEM);
    cudaFuncSetAttribute(attn_kernel, cudaFuncAttributeMaxDynamicSharedMemorySize, ATTN_SMEM);

    // ONE fused conversion kernel
    convert_all_kernel<<<(U_TOT + 255) / 256, 256>>>(
        wq, wk, wv, wo, hidden, wq_s, bq, wk_s, bk, wv_s, Wqkv, Wo, Xh, Sq, Bq);

    // fused QKV projection (single GEMM over N=6144)
    gemm_f16<<<dim3(NQKV / 128, TT / 128), 256, GEMM_SMEM>>>(
        Xh, Wqkv, Sq, Bq, NQKV, 1, nullptr, Q, K, V);

    // causal GQA flash attention -> fp16 AO (token-major)
    attn_kernel<<<dim3(SEQ / 128, NH, BSZ), 256, ATTN_SMEM>>>(Q, K, V, AO);

    // output projection -> fp32 d_out
    gemm_f16<<<dim3(HID / 128, TT / 128), 256, GEMM_SMEM>>>(
        AO, Wo, wo_s, nullptr, HID, 0, out, nullptr, nullptr, nullptr);
}

// round 16
// speedup vs baseline: 1.2563x; 1.1327x over previous
#include <cuda_runtime.h>
#include <cuda_fp16.h>
#include <cuda.h>
#include <cstdint>

typedef __half h16;

// Problem constants
#define HID   4096
#define TT    2048     // B*S tokens
#define SEQ   1024
#define BSZ   2
#define NH    32
#define NKV   8
#define HD    128
#define DKV   (NKV * HD)
#define NQKV  (HID + 2 * DKV)   // 6144 fused output columns

// ---------------- device-global scratch (no runtime allocation allowed) ----------------
__device__ __align__(128) h16   g_Xh[(size_t)TT * HID];
__device__ __align__(128) h16   g_Wqkv[(size_t)NQKV * HID];   // rows: 0..4095 Q, 4096..5119 K, 5120..6143 V
__device__ __align__(128) h16   g_Wo[(size_t)HID * HID];
__device__ __align__(128) float g_Sqkv[NQKV];
__device__ __align__(128) float g_Bqkv[NQKV];
__device__ __align__(128) h16   g_Q[(size_t)BSZ * NH * SEQ * HD];
__device__ __align__(128) h16   g_K[(size_t)BSZ * NKV * SEQ * HD];
__device__ __align__(128) h16   g_V[(size_t)BSZ * NKV * SEQ * HD];
__device__ __align__(128) h16   g_AO[(size_t)TT * HID];

// ---------------- helpers ----------------
__device__ __forceinline__ void cp16(void* s, const void* g) {
    unsigned sa = (unsigned)__cvta_generic_to_shared(s);
    asm volatile("cp.async.cg.shared.global [%0], [%1], 16;" ::"r"(sa), "l"(g));
}
__device__ __forceinline__ void cp_commit() { asm volatile("cp.async.commit_group;"); }
template <int N>
__device__ __forceinline__ void cp_waitg() { asm volatile("cp.async.wait_group %0;" ::"n"(N)); }

__device__ __forceinline__ void ldsm4(unsigned addr, unsigned (&r)[4]) {
    asm volatile("ldmatrix.sync.aligned.m8n8.x4.shared.b16 {%0,%1,%2,%3}, [%4];"
                 : "=r"(r[0]), "=r"(r[1]), "=r"(r[2]), "=r"(r[3]) : "r"(addr));
}
__device__ __forceinline__ void ldsm4t(unsigned addr, unsigned (&r)[4]) {
    asm volatile("ldmatrix.sync.aligned.m8n8.x4.trans.shared.b16 {%0,%1,%2,%3}, [%4];"
                 : "=r"(r[0]), "=r"(r[1]), "=r"(r[2]), "=r"(r[3]) : "r"(addr));
}
__device__ __forceinline__ void mma_f16(float (&c)[4], const unsigned (&a)[4], const unsigned* b) {
    asm volatile(
        "mma.sync.aligned.m16n8k16.row.col.f32.f16.f16.f32 "
        "{%0,%1,%2,%3}, {%4,%5,%6,%7}, {%8,%9}, {%0,%1,%2,%3};\n"
        : "+f"(c[0]), "+f"(c[1]), "+f"(c[2]), "+f"(c[3])
        : "r"(a[0]), "r"(a[1]), "r"(a[2]), "r"(a[3]), "r"(b[0]), "r"(b[1]));
}
__device__ __forceinline__ unsigned packh2(float a, float b) {
    __half2 t = __floats2half2_rn(a, b);
    return *reinterpret_cast<unsigned*>(&t);
}
__device__ __forceinline__ unsigned ex2h2(float a, float b) {
    __half2 t = __floats2half2_rn(a, b);
    unsigned x = *reinterpret_cast<unsigned*>(&t), p;
    asm("ex2.approx.f16x2 %0, %1;" : "=r"(p) : "r"(x));
    return p;
}
__device__ __forceinline__ float2 h2f2(unsigned p) {
    return __half22float2(*reinterpret_cast<__half2*>(&p));
}
__device__ __forceinline__ void mbar_init(unsigned bar, unsigned cnt) {
    asm volatile("mbarrier.init.shared.b64 [%0], %1;" ::"r"(bar), "r"(cnt) : "memory");
}
__device__ __forceinline__ void mbar_expect(unsigned bar, unsigned bytes) {
    asm volatile("mbarrier.arrive.expect_tx.shared.b64 _, [%0], %1;" ::"r"(bar), "r"(bytes) : "memory");
}
__device__ __forceinline__ void mbar_wait(unsigned bar, unsigned parity) {
    asm volatile(
        "{\n\t.reg .pred P;\n\t"
        "WLOOP%=:\n\t"
        "mbarrier.try_wait.parity.acquire.cta.shared::cta.b64 P, [%0], %1, 0x989680;\n\t"
        "@P bra.uni WDONE%=;\n\t"
        "bra.uni WLOOP%=;\n\t"
        "WDONE%=:\n\t}"
        ::"r"(bar), "r"(parity) : "memory");
}
__device__ __forceinline__ void tma2d(unsigned dst, const CUtensorMap* map, int x, int y, unsigned bar) {
    asm volatile(
        "cp.async.bulk.tensor.2d.shared::cta.global.tile.mbarrier::complete_tx::bytes "
        "[%0], [%1, {%2, %3}], [%4];"
        ::"r"(dst), "l"(map), "r"(x), "r"(y), "r"(bar) : "memory");
}

// ---------------- single fused conversion kernel ----------------
#define U_WQ  (HID * HID / 8)        // 2097152
#define U_WKV (DKV * HID / 8)        // 524288
#define U_XH  (TT * HID / 8)         // 1048576
#define U0 U_WQ
#define U1 (U0 + U_WKV)
#define U2 (U1 + U_WKV)
#define U3 (U2 + U_WQ)
#define U4 (U3 + U_XH)
#define U_SC 768
#define U_TOT (U4 + U_SC)

__device__ __forceinline__ void conv_i8(const int* __restrict__ src, h16* __restrict__ dst, int u) {
    const int4* wp = (const int4*)src + (size_t)u * 2;
    int4 a = wp[0], b = wp[1];
    uint4 o;
    o.x = packh2((float)a.x, (float)a.y);
    o.y = packh2((float)a.z, (float)a.w);
    o.z = packh2((float)b.x, (float)b.y);
    o.w = packh2((float)b.z, (float)b.w);
    ((uint4*)dst)[u] = o;
}
__global__ void convert_all_kernel(
    const int* __restrict__ wq, const int* __restrict__ wk,
    const int* __restrict__ wv, const int* __restrict__ wo,
    const float* __restrict__ hidden,
    const float* __restrict__ qs, const float* __restrict__ bq,
    const float* __restrict__ ks, const float* __restrict__ bk,
    const float* __restrict__ vs,
    h16* __restrict__ Wqkv, h16* __restrict__ Wo, h16* __restrict__ Xh,
    float* __restrict__ S, float* __restrict__ B) {
    int i = blockIdx.x * blockDim.x + threadIdx.x;
    if (i < U0) {
        conv_i8(wq, Wqkv, i);
    } else if (i < U1) {
        conv_i8(wk, Wqkv + (size_t)HID * HID, i - U0);
    } else if (i < U2) {
        conv_i8(wv, Wqkv + (size_t)(HID + DKV) * HID, i - U1);
    } else if (i < U3) {
        conv_i8(wo, Wo, i - U2);
    } else if (i < U4) {
        int u = i - U3;
        const float4* xp = (const float4*)hidden + (size_t)u * 2;
        float4 a = xp[0], b = xp[1];
        uint4 o;
        o.x = packh2(a.x, a.y);
        o.y = packh2(a.z, a.w);
        o.z = packh2(b.x, b.y);
        o.w = packh2(b.z, b.w);
        ((uint4*)Xh)[u] = o;
    } else if (i < U_TOT) {
        int c0 = (i - U4) * 8;
#pragma unroll
        for (int k = 0; k < 8; k++) {
            int c = c0 + k;
            if (c < HID)            { S[c] = qs[c];             B[c] = bq[c]; }
            else if (c < HID + DKV) { S[c] = ks[c - HID];       B[c] = bk[c - HID]; }
            else                    { S[c] = vs[c - HID - DKV]; B[c] = 0.f; }
        }
    }
}

// ---------------- TMA-fed fp16 GEMM: C[M,N] = A[M,K=4096] * W[N,K]^T ----------------
// 128x128 CTA tile, BK=64, 3-stage TMA+mbarrier pipeline (SW128 swizzle), occupancy 2.
// Stage = A(128x64) 16KB + B(128x64) 16KB = 32KB, no padding.
#define STG_B 32768u
#define GEMM_SMEM (1024 + 3 * 32768)   // 99328 bytes (mbarriers live in the alignment slack)

__global__ __launch_bounds__(256, 2) void gemm_tma(
    const __grid_constant__ CUtensorMap mapA,
    const __grid_constant__ CUtensorMap mapB,
    const float* __restrict__ scale, const float* __restrict__ bias,
    int N, int mode,
    float* __restrict__ outF,
    h16* __restrict__ Qp, h16* __restrict__ Kp, h16* __restrict__ Vp) {
    extern __shared__ char smraw[];
    const unsigned sraw = (unsigned)__cvta_generic_to_shared(smraw);
    const unsigned mb = sraw;                       // 3 x 8B mbarriers
    const unsigned sdata = (sraw + 1023) & ~1023u;  // 1024B-aligned stages
    const int tid = threadIdx.x, lane = tid & 31, wid = tid >> 5;
    const int mBase = blockIdx.y * 128, nBase = blockIdx.x * 128;
    const int wm = (wid & 3) * 32, wn = (wid >> 2) * 64;

    if (tid == 0)
        for (int s = 0; s < 3; s++) mbar_init(mb + 8 * s, 1);
    __syncthreads();

    auto issue = [&](int st, int kt) {
        if (tid == 0) {
            const unsigned m = mb + 8 * st;
            mbar_expect(m, STG_B);
            const unsigned dA = sdata + st * STG_B;
            tma2d(dA, &mapA, kt * 64, mBase, m);
            tma2d(dA + 16384, &mapB, kt * 64, nBase, m);
        }
    };

    float acc[2][8][4];
#pragma unroll
    for (int mi = 0; mi < 2; mi++)
#pragma unroll
        for (int nf = 0; nf < 8; nf++)
#pragma unroll
            for (int e = 0; e < 4; e++) acc[mi][nf][e] = 0.f;

    issue(0, 0);
    issue(1, 1);
    int phs = 0;  // per-stage phase bits

    // ks-invariant swizzled ldsm byte offsets within a stage
    // A: row = wm + mi*16 + (lane&15), col byte = ks*32 + (lane>>4)*16
    // B: row = wn + ni*16 + (lane&7) + ((lane>>4)<<3), col byte = ks*32 + ((lane>>3)&1)*16
    const unsigned aRowByte0 = (unsigned)(wm + (lane & 15)) * 128 + (unsigned)(lane >> 4) * 16;
    const unsigned bColByte = (unsigned)((lane >> 3) & 1) * 16;
    const unsigned bRowBase = (unsigned)(wn + (lane & 7) + ((lane >> 4) << 3)) * 128;

    const int KT = HID / 64;  // 64
    for (int kt = 0; kt < KT; kt++) {
        const int st = kt % 3;
        __syncthreads();                       // all warps done with stage (kt+2)%3 (read at kt-1)
        if (kt + 2 < KT) issue((kt + 2) % 3, kt + 2);
        mbar_wait(mb + 8 * st, (phs >> st) & 1);
        phs ^= 1 << st;

        const unsigned ab = sdata + st * STG_B;
        const unsigned bb = ab + 16384;
#pragma unroll
        for (int ks = 0; ks < 4; ks++) {
            const unsigned kByte = (unsigned)(ks * 32);
            unsigned aF[2][4], bF[4][4];
#pragma unroll
            for (int mi = 0; mi < 2; mi++) {
                unsigned byte = aRowByte0 + (unsigned)(mi * 16) * 128 + kByte;
                ldsm4(ab + (byte ^ ((byte >> 3) & 0x70)), aF[mi]);
            }
#pragma unroll
            for (int ni = 0; ni < 4; ni++) {
                unsigned byte = bRowBase + (unsigned)(ni * 16) * 128 + kByte + bColByte;
                ldsm4(bb + (byte ^ ((byte >> 3) & 0x70)), bF[ni]);
            }
#pragma unroll
            for (int mi = 0; mi < 2; mi++)
#pragma unroll
                for (int ni = 0; ni < 4; ni++) {
                    mma_f16(acc[mi][2 * ni],     aF[mi], &bF[ni][0]);
                    mma_f16(acc[mi][2 * ni + 1], aF[mi], &bF[ni][2]);
                }
        }
    }

    // ---- epilogue: paired stores (adjacent columns)
#pragma unroll
    for (int mi = 0; mi < 2; mi++)
#pragma unroll
        for (int nf = 0; nf < 8; nf++)
#pragma unroll
            for (int p = 0; p < 2; p++) {
                const int r = mBase + wm + mi * 16 + (lane >> 2) + p * 8;
                const int c = nBase + wn + nf * 8 + 2 * (lane & 3);
                float va = acc[mi][nf][2 * p]     * scale[c];
                float vb = acc[mi][nf][2 * p + 1] * scale[c + 1];
                if (bias) { va += bias[c]; vb += bias[c + 1]; }
                if (mode == 0) {
                    *reinterpret_cast<float2*>(outF + (size_t)r * N + c) = make_float2(va, vb);
                } else {
                    h16* dst; int nh, cb;
                    if (c < HID)            { dst = Qp; nh = NH;  cb = c; }
                    else if (c < HID + DKV) { dst = Kp; nh = NKV; cb = c - HID; }
                    else                    { dst = Vp; nh = NKV; cb = c - HID - DKV; }
                    const int head = cb >> 7, d = cb & 127;
                    const int bb2 = r >> 10, ss = r & 1023;
                    const size_t idx = (((size_t)(bb2 * nh + head)) * SEQ + ss) * HD + d;
                    *reinterpret_cast<unsigned*>(dst + idx) = packh2(va, vb);
                }
            }
}

// ---------------- flash attention (causal, GQA), single-term fp16 ----------------
#define QST 136
#define ASTG_E (128 * QST)            // 34816 B per stage
#define ATTN_SMEM (3 * ASTG_E * 2)    // 104448 bytes

__global__ __launch_bounds__(256) void attn_kernel(
    const h16* __restrict__ Q, const h16* __restrict__ K, const h16* __restrict__ V,
    h16* __restrict__ AO) {
    extern __shared__ h16 sm[];
    const int tid = threadIdx.x, lane = tid & 31, wid = tid >> 5;
    const int qi = (int)gridDim.x - 1 - (int)blockIdx.x;  // heavy tiles first
    const int h = blockIdx.y, b = blockIdx.z;
    const int kvh = h >> 2;  // GROUPS = 4
    const unsigned sbase = (unsigned)__cvta_generic_to_shared(sm);
    const float SCLG = 0.08838834764831845f * 1.4426950408889634f;
    const int wm = wid * 16;

    const size_t qoff = (((size_t)(b * NH + h)) * SEQ + qi * 128) * HD;
    {
#pragma unroll
        for (int i = 0; i < 8; i++) {
            int c = tid + i * 256;
            int row = c >> 4, cb = (c & 15) * 8;
            cp16(sm + row * QST + cb, Q + qoff + row * HD + cb);
        }
        cp_commit();
        cp_waitg<0>();
        __syncthreads();
    }
    unsigned qf[8][4];
#pragma unroll
    for (int ks = 0; ks < 8; ks++) {
        int row = wm + (lane & 15);
        int col = ks * 16 + (lane >> 4) * 8;
        ldsm4(sbase + (unsigned)(row * QST + col) * 2, qf[ks]);
    }
    __syncthreads();

    const size_t kvbase = ((size_t)(b * NKV + kvh)) * SEQ * HD;
    auto loadKV = [&](int slot, int j) {
        h16* s = sm + slot * ASTG_E;
        const size_t koff = kvbase + (size_t)(j * 64) * HD;
#pragma unroll
        for (int i = 0; i < 8; i++) {
            int idx = tid + i * 256;
            int r = idx >> 4, q = (idx & 15) * 8;
            const h16* src = (r < 64) ? K + koff + (size_t)r * HD + q
                                      : V + koff + (size_t)(r - 64) * HD + q;
            cp16(s + r * QST + q, src);
        }
    };

    float o[16][4];
#pragma unroll
    for (int nf = 0; nf < 16; nf++)
#pragma unroll
        for (int e = 0; e < 4; e++) o[nf][e] = 0.f;
    float m0 = -1e30f, m1 = -1e30f, l0 = 0.f, l1 = 0.f;

    const int jn = 2 * qi + 2;
    loadKV(0, 0); cp_commit();
    if (jn > 1) { loadKV(1, 1); cp_commit(); }

    for (int j = 0; j < jn; j++) {
        if (j + 1 < jn) cp_waitg<1>(); else cp_waitg<0>();
        __syncthreads();
        if (j + 2 < jn) { loadKV((j + 2) % 3, j + 2); cp_commit(); }

        const unsigned sb = sbase + (unsigned)((j % 3) * ASTG_E) * 2;
        const unsigned khb = sb;
        const unsigned vhb = sb + (unsigned)(64 * QST) * 2;

        float s4[8][4];
#pragma unroll
        for (int nf = 0; nf < 8; nf++)
#pragma unroll
            for (int e = 0; e < 4; e++) s4[nf][e] = 0.f;
#pragma unroll
        for (int ks = 0; ks < 8; ks++) {
            unsigned kf[4][4];
#pragma unroll
            for (int ni = 0; ni < 4; ni++) {
                int row = ni * 16 + (lane & 7) + ((lane >> 4) << 3);
                int col = ks * 16 + ((lane >> 3) & 1) * 8;
                ldsm4(khb + (unsigned)(row * QST + col) * 2, kf[ni]);
            }
#pragma unroll
            for (int ni = 0; ni < 4; ni++) {
                mma_f16(s4[2 * ni],     qf[ks], &kf[ni][0]);
                mma_f16(s4[2 * ni + 1], qf[ks], &kf[ni][2]);
            }
        }

        const int rbase = qi * 128 + wm + (lane >> 2);
        const bool needMask = (j >= 2 * qi);
#pragma unroll
        for (int nf = 0; nf < 8; nf++)
#pragma unroll
            for (int e = 0; e < 4; e++) {
                s4[nf][e] *= SCLG;
                if (needMask) {
                    int r = rbase + ((e >> 1) << 3);
                    int cg = j * 64 + nf * 8 + 2 * (lane & 3) + (e & 1);
                    if (cg > r) s4[nf][e] = -1e30f;
                }
            }

        float mx0 = -1e30f, mx1 = -1e30f;
#pragma unroll
        for (int nf = 0; nf < 8; nf++) {
            mx0 = fmaxf(mx0, fmaxf(s4[nf][0], s4[nf][1]));
            mx1 = fmaxf(mx1, fmaxf(s4[nf][2], s4[nf][3]));
        }
        mx0 = fmaxf(mx0, __shfl_xor_sync(0xffffffffu, mx0, 1));
        mx0 = fmaxf(mx0, __shfl_xor_sync(0xffffffffu, mx0, 2));
        mx1 = fmaxf(mx1, __shfl_xor_sync(0xffffffffu, mx1, 1));
        mx1 = fmaxf(mx1, __shfl_xor_sync(0xffffffffu, mx1, 2));
        float mn0 = fmaxf(m0, mx0), mn1 = fmaxf(m1, mx1);
        float c0 = exp2f(m0 - mn0), c1 = exp2f(m1 - mn1);
        m0 = mn0;
        m1 = mn1;

        float rs0 = 0.f, rs1 = 0.f;
        unsigned pfrag[4][4];
#pragma unroll
        for (int nf = 0; nf < 8; nf++) {
            unsigned pa = ex2h2(s4[nf][0] - mn0, s4[nf][1] - mn0);
            unsigned pb = ex2h2(s4[nf][2] - mn1, s4[nf][3] - mn1);
            float2 fa = h2f2(pa), fb = h2f2(pb);
            rs0 += fa.x + fa.y;
            rs1 += fb.x + fb.y;
            int kc = nf >> 1, sub = nf & 1;
            pfrag[kc][2 * sub] = pa;
            pfrag[kc][2 * sub + 1] = pb;
        }
        rs0 += __shfl_xor_sync(0xffffffffu, rs0, 1);
        rs0 += __shfl_xor_sync(0xffffffffu, rs0, 2);
        rs1 += __shfl_xor_sync(0xffffffffu, rs1, 1);
        rs1 += __shfl_xor_sync(0xffffffffu, rs1, 2);
        l0 = l0 * c0 + rs0;
        l1 = l1 * c1 + rs1;
#pragma unroll
        for (int nf = 0; nf < 16; nf++) {
            o[nf][0] *= c0;
            o[nf][1] *= c0;
            o[nf][2] *= c1;
            o[nf][3] *= c1;
        }

#pragma unroll
        for (int kc = 0; kc < 4; kc++) {
#pragma unroll
            for (int dg = 0; dg < 8; dg++) {
                int row = kc * 16 + (lane & 15);
                int col = dg * 16 + (lane >> 4) * 8;
                unsigned vf[4];
                ldsm4t(vhb + (unsigned)(row * QST + col) * 2, vf);
                mma_f16(o[2 * dg],     pfrag[kc], &vf[0]);
                mma_f16(o[2 * dg + 1], pfrag[kc], &vf[2]);
            }
        }
    }

    float inv0 = 1.f / l0, inv1 = 1.f / l1;
    const int tok0 = b * SEQ + qi * 128 + wm + (lane >> 2);
#pragma unroll
    for (int nf = 0; nf < 16; nf++)
#pragma unroll
        for (int p = 0; p < 2; p++) {
            int r = tok0 + p * 8;
            int d = nf * 8 + 2 * (lane & 3);
            float va = o[nf][2 * p] * ((p == 0) ? inv0 : inv1);
            float vb = o[nf][2 * p + 1] * ((p == 0) ? inv0 : inv1);
            *reinterpret_cast<unsigned*>(AO + (size_t)r * HID + h * HD + d) = packh2(va, vb);
        }
}

// ---------------- host launch ----------------
typedef CUresult (*EncodeFn)(
    CUtensorMap*, CUtensorMapDataType, cuuint32_t, void*,
    const cuuint64_t*, const cuuint64_t*, const cuuint32_t*, const cuuint32_t*,
    CUtensorMapInterleave, CUtensorMapSwizzle, CUtensorMapL2promotion, CUtensorMapFloatOOBfill);

static void make_map(EncodeFn fn, CUtensorMap* map, void* base, uint64_t rows) {
    cuuint64_t dims[2] = {(cuuint64_t)HID, (cuuint64_t)rows};
    cuuint64_t strides[1] = {(cuuint64_t)HID * 2};
    cuuint32_t box[2] = {64, 128};
    cuuint32_t estr[2] = {1, 1};
    fn(map, CU_TENSOR_MAP_DATA_TYPE_FLOAT16, 2, base, dims, strides, box, estr,
       CU_TENSOR_MAP_INTERLEAVE_NONE, CU_TENSOR_MAP_SWIZZLE_128B,
       CU_TENSOR_MAP_L2_PROMOTION_L2_128B, CU_TENSOR_MAP_FLOAT_OOB_FILL_NONE);
}

extern "C" void kernel_launch(void* const* d_in, const int* in_sizes, int n_in,
                              void* d_out, int out_size) {
    (void)in_sizes; (void)n_in; (void)out_size;
    const float* hidden = (const float*)d_in[0];
    const int*   wq   = (const int*)d_in[2];
    const float* wq_s = (const float*)d_in[3];
    const float* bq   = (const float*)d_in[4];
    const int*   wk   = (const int*)d_in[5];
    const float* wk_s = (const float*)d_in[6];
    const float* bk   = (const float*)d_in[7];
    const int*   wv   = (const int*)d_in[8];
    const float* wv_s = (const float*)d_in[9];
    const int*   wo   = (const int*)d_in[10];
    const float* wo_s = (const float*)d_in[11];
    float* out = (float*)d_out;

    h16 *Xh, *Wqkv, *Wo, *Q, *K, *V, *AO;
    float *Sq, *Bq;
    cudaGetSymbolAddress((void**)&Xh,   g_Xh);
    cudaGetSymbolAddress((void**)&Wqkv, g_Wqkv);
    cudaGetSymbolAddress((void**)&Wo,   g_Wo);
    cudaGetSymbolAddress((void**)&Sq,   g_Sqkv);
    cudaGetSymbolAddress((void**)&Bq,   g_Bqkv);
    cudaGetSymbolAddress((void**)&Q,    g_Q);
    cudaGetSymbolAddress((void**)&K,    g_K);
    cudaGetSymbolAddress((void**)&V,    g_V);
    cudaGetSymbolAddress((void**)&AO,   g_AO);

    // resolve cuTensorMapEncodeTiled through the runtime (no -lcuda needed)
    EncodeFn enc = nullptr;
    {
        void* fnp = nullptr;
        cudaDriverEntryPointQueryResult qres;
        cudaGetDriverEntryPoint("cuTensorMapEncodeTiled", &fnp, cudaEnableDefault, &qres);
        enc = (EncodeFn)fnp;
    }
    CUtensorMap mapX, mapWqkv, mapAO, mapWo;
    make_map(enc, &mapX,    Xh,   TT);
    make_map(enc, &mapWqkv, Wqkv, NQKV);
    make_map(enc, &mapAO,   AO,   TT);
    make_map(enc, &mapWo,   Wo,   HID);

    cudaFuncSetAttribute(gemm_tma, cudaFuncAttributeMaxDynamicSharedMemorySize, GEMM_SMEM);
    cudaFuncSetAttribute(attn_kernel, cudaFuncAttributeMaxDynamicSharedMemorySize, ATTN_SMEM);

    // ONE fused conversion kernel
    convert_all_kernel<<<(U_TOT + 255) / 256, 256>>>(
        wq, wk, wv, wo, hidden, wq_s, bq, wk_s, bk, wv_s, Wqkv, Wo, Xh, Sq, Bq);

    // fused QKV projection (single GEMM over N=6144)
    gemm_tma<<<dim3(NQKV / 128, TT / 128), 256, GEMM_SMEM>>>(
        mapX, mapWqkv, Sq, Bq, NQKV, 1, nullptr, Q, K, V);

    // causal GQA flash attention -> fp16 AO (token-major)
    attn_kernel<<<dim3(SEQ / 128, NH, BSZ), 256, ATTN_SMEM>>>(Q, K, V, AO);

    // output projection -> fp32 d_out
    gemm_tma<<<dim3(HID / 128, TT / 128), 256, GEMM_SMEM>>>(
        mapAO, mapWo, wo_s, nullptr, HID, 0, out, nullptr, nullptr, nullptr);
}

// round 17
// speedup vs baseline: 1.2908x; 1.0274x over previous
#include <cuda_runtime.h>
#include <cuda_fp16.h>
#include <cuda.h>
#include <cstdint>

typedef __half h16;

// Problem constants
#define HID   4096
#define TT    2048     // B*S tokens
#define SEQ   1024
#define BSZ   2
#define NH    32
#define NKV   8
#define HD    128
#define DKV   (NKV * HD)
#define NQKV  (HID + 2 * DKV)   // 6144 fused output columns

// ---------------- device-global scratch (no runtime allocation allowed) ----------------
__device__ __align__(128) h16   g_Xh[(size_t)TT * HID];
__device__ __align__(128) h16   g_Wqkv[(size_t)NQKV * HID];   // rows: 0..4095 Q, 4096..5119 K, 5120..6143 V
__device__ __align__(128) h16   g_Wo[(size_t)HID * HID];
__device__ __align__(128) float g_Sqkv[NQKV];
__device__ __align__(128) float g_Bqkv[NQKV];
__device__ __align__(128) h16   g_Q[(size_t)BSZ * NH * SEQ * HD];
__device__ __align__(128) h16   g_K[(size_t)BSZ * NKV * SEQ * HD];
__device__ __align__(128) h16   g_V[(size_t)BSZ * NKV * SEQ * HD];
__device__ __align__(128) h16   g_AO[(size_t)TT * HID];

// ---------------- helpers ----------------
__device__ __forceinline__ void cp16(void* s, const void* g) {
    unsigned sa = (unsigned)__cvta_generic_to_shared(s);
    asm volatile("cp.async.cg.shared.global [%0], [%1], 16;" ::"r"(sa), "l"(g));
}
__device__ __forceinline__ void cp_commit() { asm volatile("cp.async.commit_group;"); }
template <int N>
__device__ __forceinline__ void cp_waitg() { asm volatile("cp.async.wait_group %0;" ::"n"(N)); }

__device__ __forceinline__ void ldsm4(unsigned addr, unsigned (&r)[4]) {
    asm volatile("ldmatrix.sync.aligned.m8n8.x4.shared.b16 {%0,%1,%2,%3}, [%4];"
                 : "=r"(r[0]), "=r"(r[1]), "=r"(r[2]), "=r"(r[3]) : "r"(addr));
}
__device__ __forceinline__ void ldsm4t(unsigned addr, unsigned (&r)[4]) {
    asm volatile("ldmatrix.sync.aligned.m8n8.x4.trans.shared.b16 {%0,%1,%2,%3}, [%4];"
                 : "=r"(r[0]), "=r"(r[1]), "=r"(r[2]), "=r"(r[3]) : "r"(addr));
}
__device__ __forceinline__ void mma_f16(float (&c)[4], const unsigned (&a)[4], const unsigned* b) {
    asm volatile(
        "mma.sync.aligned.m16n8k16.row.col.f32.f16.f16.f32 "
        "{%0,%1,%2,%3}, {%4,%5,%6,%7}, {%8,%9}, {%0,%1,%2,%3};\n"
        : "+f"(c[0]), "+f"(c[1]), "+f"(c[2]), "+f"(c[3])
        : "r"(a[0]), "r"(a[1]), "r"(a[2]), "r"(a[3]), "r"(b[0]), "r"(b[1]));
}
__device__ __forceinline__ unsigned packh2(float a, float b) {
    __half2 t = __floats2half2_rn(a, b);
    return *reinterpret_cast<unsigned*>(&t);
}
__device__ __forceinline__ unsigned ex2h2(float a, float b) {
    __half2 t = __floats2half2_rn(a, b);
    unsigned x = *reinterpret_cast<unsigned*>(&t), p;
    asm("ex2.approx.f16x2 %0, %1;" : "=r"(p) : "r"(x));
    return p;
}
__device__ __forceinline__ float2 h2f2(unsigned p) {
    return __half22float2(*reinterpret_cast<__half2*>(&p));
}
__device__ __forceinline__ void mbar_init(unsigned bar, unsigned cnt) {
    asm volatile("mbarrier.init.shared.b64 [%0], %1;" ::"r"(bar), "r"(cnt) : "memory");
}
__device__ __forceinline__ void mbar_expect(unsigned bar, unsigned bytes) {
    asm volatile("mbarrier.arrive.expect_tx.shared.b64 _, [%0], %1;" ::"r"(bar), "r"(bytes) : "memory");
}
__device__ __forceinline__ void mbar_wait(unsigned bar, unsigned parity) {
    asm volatile(
        "{\n\t.reg .pred P;\n\t"
        "WLOOP%=:\n\t"
        "mbarrier.try_wait.parity.acquire.cta.shared::cta.b64 P, [%0], %1, 0x989680;\n\t"
        "@P bra.uni WDONE%=;\n\t"
        "bra.uni WLOOP%=;\n\t"
        "WDONE%=:\n\t}"
        ::"r"(bar), "r"(parity) : "memory");
}
__device__ __forceinline__ void tma2d(unsigned dst, const CUtensorMap* map, int x, int y, unsigned bar) {
    asm volatile(
        "cp.async.bulk.tensor.2d.shared::cta.global.tile.mbarrier::complete_tx::bytes "
        "[%0], [%1, {%2, %3}], [%4];"
        ::"r"(dst), "l"(map), "r"(x), "r"(y), "r"(bar) : "memory");
}
__device__ __forceinline__ unsigned sw(unsigned byte) { return byte ^ ((byte >> 3) & 0x70); }

// ---------------- single fused conversion kernel ----------------
#define U_WQ  (HID * HID / 8)
#define U_WKV (DKV * HID / 8)
#define U_XH  (TT * HID / 8)
#define U0 U_WQ
#define U1 (U0 + U_WKV)
#define U2 (U1 + U_WKV)
#define U3 (U2 + U_WQ)
#define U4 (U3 + U_XH)
#define U_SC 768
#define U_TOT (U4 + U_SC)

__device__ __forceinline__ void conv_i8(const int* __restrict__ src, h16* __restrict__ dst, int u) {
    const int4* wp = (const int4*)src + (size_t)u * 2;
    int4 a = wp[0], b = wp[1];
    uint4 o;
    o.x = packh2((float)a.x, (float)a.y);
    o.y = packh2((float)a.z, (float)a.w);
    o.z = packh2((float)b.x, (float)b.y);
    o.w = packh2((float)b.z, (float)b.w);
    ((uint4*)dst)[u] = o;
}
__global__ void convert_all_kernel(
    const int* __restrict__ wq, const int* __restrict__ wk,
    const int* __restrict__ wv, const int* __restrict__ wo,
    const float* __restrict__ hidden,
    const float* __restrict__ qs, const float* __restrict__ bq,
    const float* __restrict__ ks, const float* __restrict__ bk,
    const float* __restrict__ vs,
    h16* __restrict__ Wqkv, h16* __restrict__ Wo, h16* __restrict__ Xh,
    float* __restrict__ S, float* __restrict__ B) {
    int i = blockIdx.x * blockDim.x + threadIdx.x;
    if (i < U0) {
        conv_i8(wq, Wqkv, i);
    } else if (i < U1) {
        conv_i8(wk, Wqkv + (size_t)HID * HID, i - U0);
    } else if (i < U2) {
        conv_i8(wv, Wqkv + (size_t)(HID + DKV) * HID, i - U1);
    } else if (i < U3) {
        conv_i8(wo, Wo, i - U2);
    } else if (i < U4) {
        int u = i - U3;
        const float4* xp = (const float4*)hidden + (size_t)u * 2;
        float4 a = xp[0], b = xp[1];
        uint4 o;
        o.x = packh2(a.x, a.y);
        o.y = packh2(a.z, a.w);
        o.z = packh2(b.x, b.y);
        o.w = packh2(b.z, b.w);
        ((uint4*)Xh)[u] = o;
    } else if (i < U_TOT) {
        int c0 = (i - U4) * 8;
#pragma unroll
        for (int k = 0; k < 8; k++) {
            int c = c0 + k;
            if (c < HID)            { S[c] = qs[c];             B[c] = bq[c]; }
            else if (c < HID + DKV) { S[c] = ks[c - HID];       B[c] = bk[c - HID]; }
            else                    { S[c] = vs[c - HID - DKV]; B[c] = 0.f; }
        }
    }
}

// ---------------- TMA-fed fp16 GEMM (unchanged from R15 win) ----------------
#define STG_B 32768u
#define GEMM_SMEM (1024 + 3 * 32768)

__global__ __launch_bounds__(256, 2) void gemm_tma(
    const __grid_constant__ CUtensorMap mapA,
    const __grid_constant__ CUtensorMap mapB,
    const float* __restrict__ scale, const float* __restrict__ bias,
    int N, int mode,
    float* __restrict__ outF,
    h16* __restrict__ Qp, h16* __restrict__ Kp, h16* __restrict__ Vp) {
    extern __shared__ char smraw[];
    const unsigned sraw = (unsigned)__cvta_generic_to_shared(smraw);
    const unsigned mb = sraw;
    const unsigned sdata = (sraw + 1023) & ~1023u;
    const int tid = threadIdx.x, lane = tid & 31, wid = tid >> 5;
    const int mBase = blockIdx.y * 128, nBase = blockIdx.x * 128;
    const int wm = (wid & 3) * 32, wn = (wid >> 2) * 64;

    if (tid == 0)
        for (int s = 0; s < 3; s++) mbar_init(mb + 8 * s, 1);
    __syncthreads();

    auto issue = [&](int st, int kt) {
        if (tid == 0) {
            const unsigned m = mb + 8 * st;
            mbar_expect(m, STG_B);
            const unsigned dA = sdata + st * STG_B;
            tma2d(dA, &mapA, kt * 64, mBase, m);
            tma2d(dA + 16384, &mapB, kt * 64, nBase, m);
        }
    };

    float acc[2][8][4];
#pragma unroll
    for (int mi = 0; mi < 2; mi++)
#pragma unroll
        for (int nf = 0; nf < 8; nf++)
#pragma unroll
            for (int e = 0; e < 4; e++) acc[mi][nf][e] = 0.f;

    issue(0, 0);
    issue(1, 1);
    int phs = 0;

    const unsigned aRowByte0 = (unsigned)(wm + (lane & 15)) * 128 + (unsigned)(lane >> 4) * 16;
    const unsigned bColByte = (unsigned)((lane >> 3) & 1) * 16;
    const unsigned bRowBase = (unsigned)(wn + (lane & 7) + ((lane >> 4) << 3)) * 128;

    const int KT = HID / 64;
    for (int kt = 0; kt < KT; kt++) {
        const int st = kt % 3;
        __syncthreads();
        if (kt + 2 < KT) issue((kt + 2) % 3, kt + 2);
        mbar_wait(mb + 8 * st, (phs >> st) & 1);
        phs ^= 1 << st;

        const unsigned ab = sdata + st * STG_B;
        const unsigned bb = ab + 16384;
#pragma unroll
        for (int ks = 0; ks < 4; ks++) {
            const unsigned kByte = (unsigned)(ks * 32);
            unsigned aF[2][4], bF[4][4];
#pragma unroll
            for (int mi = 0; mi < 2; mi++) {
                unsigned byte = aRowByte0 + (unsigned)(mi * 16) * 128 + kByte;
                ldsm4(ab + sw(byte), aF[mi]);
            }
#pragma unroll
            for (int ni = 0; ni < 4; ni++) {
                unsigned byte = bRowBase + (unsigned)(ni * 16) * 128 + kByte + bColByte;
                ldsm4(bb + sw(byte), bF[ni]);
            }
#pragma unroll
            for (int mi = 0; mi < 2; mi++)
#pragma unroll
                for (int ni = 0; ni < 4; ni++) {
                    mma_f16(acc[mi][2 * ni],     aF[mi], &bF[ni][0]);
                    mma_f16(acc[mi][2 * ni + 1], aF[mi], &bF[ni][2]);
                }
        }
    }

#pragma unroll
    for (int mi = 0; mi < 2; mi++)
#pragma unroll
        for (int nf = 0; nf < 8; nf++)
#pragma unroll
            for (int p = 0; p < 2; p++) {
                const int r = mBase + wm + mi * 16 + (lane >> 2) + p * 8;
                const int c = nBase + wn + nf * 8 + 2 * (lane & 3);
                float va = acc[mi][nf][2 * p]     * scale[c];
                float vb = acc[mi][nf][2 * p + 1] * scale[c + 1];
                if (bias) { va += bias[c]; vb += bias[c + 1]; }
                if (mode == 0) {
                    *reinterpret_cast<float2*>(outF + (size_t)r * N + c) = make_float2(va, vb);
                } else {
                    h16* dst; int nh, cb;
                    if (c < HID)            { dst = Qp; nh = NH;  cb = c; }
                    else if (c < HID + DKV) { dst = Kp; nh = NKV; cb = c - HID; }
                    else                    { dst = Vp; nh = NKV; cb = c - HID - DKV; }
                    const int head = cb >> 7, d = cb & 127;
                    const int bb2 = r >> 10, ss = r & 1023;
                    const size_t idx = (((size_t)(bb2 * nh + head)) * SEQ + ss) * HD + d;
                    *reinterpret_cast<unsigned*>(dst + idx) = packh2(va, vb);
                }
            }
}

// ---------------- flash attention with TMA KV pipeline ----------------
// Stage = K(64x128) 16KB + V(64x128) 16KB, each as two 64-col SW128 boxes of 8KB.
#define QST 136
#define ATT_STG 32768u
#define ATTN_SMEM (1024 + 3 * 32768)   // 99328; Q staged temporarily in stage area

__global__ __launch_bounds__(256) void attn_kernel(
    const __grid_constant__ CUtensorMap mapK,
    const __grid_constant__ CUtensorMap mapV,
    const h16* __restrict__ Q, h16* __restrict__ AO) {
    extern __shared__ char smraw[];
    const unsigned sraw = (unsigned)__cvta_generic_to_shared(smraw);
    const unsigned mb = sraw;
    const unsigned sdata = (sraw + 1023) & ~1023u;
    h16* smq = (h16*)(smraw + (sdata - sraw));  // generic pointer to stage area (Q staging)
    const int tid = threadIdx.x, lane = tid & 31, wid = tid >> 5;
    const int qi = (int)gridDim.x - 1 - (int)blockIdx.x;  // heavy tiles first
    const int h = blockIdx.y, b = blockIdx.z;
    const int kvh = h >> 2;  // GROUPS = 4
    const float SCLG = 0.08838834764831845f * 1.4426950408889634f;
    const int wm = wid * 16;

    if (tid == 0)
        for (int s = 0; s < 3; s++) mbar_init(mb + 8 * s, 1);
    __syncthreads();

    // ---- stage Q tile (128x128) through stage smem into register fragments
    const size_t qoff = (((size_t)(b * NH + h)) * SEQ + qi * 128) * HD;
    {
#pragma unroll
        for (int i = 0; i < 8; i++) {
            int c = tid + i * 256;
            int row = c >> 4, cb = (c & 15) * 8;
            cp16(smq + row * QST + cb, Q + qoff + row * HD + cb);
        }
        cp_commit();
        cp_waitg<0>();
        __syncthreads();
    }
    unsigned qf[8][4];
#pragma unroll
    for (int ks = 0; ks < 8; ks++) {
        int row = wm + (lane & 15);
        int col = ks * 16 + (lane >> 4) * 8;
        ldsm4(sdata + (unsigned)(row * QST + col) * 2, qf[ks]);
    }
    __syncthreads();

    const int kvrow0 = (b * NKV + kvh) * SEQ;
    auto issueKV = [&](int st, int j) {
        if (tid == 0) {
            const unsigned m = mb + 8 * st;
            mbar_expect(m, ATT_STG);
            const unsigned d = sdata + st * ATT_STG;
            const int y = kvrow0 + j * 64;
            tma2d(d,         &mapK, 0,  y, m);
            tma2d(d + 8192,  &mapK, 64, y, m);
            tma2d(d + 16384, &mapV, 0,  y, m);
            tma2d(d + 24576, &mapV, 64, y, m);
        }
    };

    float o[16][4];
#pragma unroll
    for (int nf = 0; nf < 16; nf++)
#pragma unroll
        for (int e = 0; e < 4; e++) o[nf][e] = 0.f;
    float m0 = -1e30f, m1 = -1e30f, l0 = 0.f, l1 = 0.f;

    const int jn = 2 * qi + 2;
    issueKV(0, 0);
    if (jn > 1) issueKV(1, 1);
    int phs = 0;

    for (int j = 0; j < jn; j++) {
        const int st = j % 3;
        __syncthreads();
        if (j + 2 < jn) issueKV((j + 2) % 3, j + 2);
        mbar_wait(mb + 8 * st, (phs >> st) & 1);
        phs ^= 1 << st;

        const unsigned kb = sdata + st * ATT_STG;
        const unsigned vb = kb + 16384;

        // ---- scores S = Q.K^T
        float s4[8][4];
#pragma unroll
        for (int nf = 0; nf < 8; nf++)
#pragma unroll
            for (int e = 0; e < 4; e++) s4[nf][e] = 0.f;
#pragma unroll
        for (int ks = 0; ks < 8; ks++) {
            unsigned kf[4][4];
#pragma unroll
            for (int ni = 0; ni < 4; ni++) {
                int row = ni * 16 + (lane & 7) + ((lane >> 4) << 3);
                int col = ks * 16 + ((lane >> 3) & 1) * 8;
                unsigned blk = (unsigned)(col >> 6) * 8192;
                unsigned byte = (unsigned)row * 128 + (unsigned)(col & 63) * 2;
                ldsm4(kb + blk + sw(byte), kf[ni]);
            }
#pragma unroll
            for (int ni = 0; ni < 4; ni++) {
                mma_f16(s4[2 * ni],     qf[ks], &kf[ni][0]);
                mma_f16(s4[2 * ni + 1], qf[ks], &kf[ni][2]);
            }
        }

        // ---- fold scale*log2e + causal mask
        const int rbase = qi * 128 + wm + (lane >> 2);
        const bool needMask = (j >= 2 * qi);
#pragma unroll
        for (int nf = 0; nf < 8; nf++)
#pragma unroll
            for (int e = 0; e < 4; e++) {
                s4[nf][e] *= SCLG;
                if (needMask) {
                    int r = rbase + ((e >> 1) << 3);
                    int cg = j * 64 + nf * 8 + 2 * (lane & 3) + (e & 1);
                    if (cg > r) s4[nf][e] = -1e30f;
                }
            }

        // ---- online softmax, exp in f16x2
        float mx0 = -1e30f, mx1 = -1e30f;
#pragma unroll
        for (int nf = 0; nf < 8; nf++) {
            mx0 = fmaxf(mx0, fmaxf(s4[nf][0], s4[nf][1]));
            mx1 = fmaxf(mx1, fmaxf(s4[nf][2], s4[nf][3]));
        }
        mx0 = fmaxf(mx0, __shfl_xor_sync(0xffffffffu, mx0, 1));
        mx0 = fmaxf(mx0, __shfl_xor_sync(0xffffffffu, mx0, 2));
        mx1 = fmaxf(mx1, __shfl_xor_sync(0xffffffffu, mx1, 1));
        mx1 = fmaxf(mx1, __shfl_xor_sync(0xffffffffu, mx1, 2));
        float mn0 = fmaxf(m0, mx0), mn1 = fmaxf(m1, mx1);
        float c0 = exp2f(m0 - mn0), c1 = exp2f(m1 - mn1);
        m0 = mn0;
        m1 = mn1;

        float rs0 = 0.f, rs1 = 0.f;
        unsigned pfrag[4][4];
#pragma unroll
        for (int nf = 0; nf < 8; nf++) {
            unsigned pa = ex2h2(s4[nf][0] - mn0, s4[nf][1] - mn0);
            unsigned pb = ex2h2(s4[nf][2] - mn1, s4[nf][3] - mn1);
            float2 fa = h2f2(pa), fb = h2f2(pb);
            rs0 += fa.x + fa.y;
            rs1 += fb.x + fb.y;
            int kc = nf >> 1, sub = nf & 1;
            pfrag[kc][2 * sub] = pa;
            pfrag[kc][2 * sub + 1] = pb;
        }
        rs0 += __shfl_xor_sync(0xffffffffu, rs0, 1);
        rs0 += __shfl_xor_sync(0xffffffffu, rs0, 2);
        rs1 += __shfl_xor_sync(0xffffffffu, rs1, 1);
        rs1 += __shfl_xor_sync(0xffffffffu, rs1, 2);
        l0 = l0 * c0 + rs0;
        l1 = l1 * c1 + rs1;
#pragma unroll
        for (int nf = 0; nf < 16; nf++) {
            o[nf][0] *= c0;
            o[nf][1] *= c0;
            o[nf][2] *= c1;
            o[nf][3] *= c1;
        }

        // ---- O += P.V
#pragma unroll
        for (int kc = 0; kc < 4; kc++) {
#pragma unroll
            for (int dg = 0; dg < 8; dg++) {
                int row = kc * 16 + (lane & 15);
                int col = dg * 16 + (lane >> 4) * 8;
                unsigned blk = (unsigned)(col >> 6) * 8192;
                unsigned byte = (unsigned)row * 128 + (unsigned)(col & 63) * 2;
                unsigned vf[4];
                ldsm4t(vb + blk + sw(byte), vf);
                mma_f16(o[2 * dg],     pfrag[kc], &vf[0]);
                mma_f16(o[2 * dg + 1], pfrag[kc], &vf[2]);
            }
        }
    }

    // ---- epilogue: normalize, write fp16 token-major [tok][h*128+d] (paired stores)
    float inv0 = 1.f / l0, inv1 = 1.f / l1;
    const int tok0 = b * SEQ + qi * 128 + wm + (lane >> 2);
#pragma unroll
    for (int nf = 0; nf < 16; nf++)
#pragma unroll
        for (int p = 0; p < 2; p++) {
            int r = tok0 + p * 8;
            int d = nf * 8 + 2 * (lane & 3);
            float va = o[nf][2 * p] * ((p == 0) ? inv0 : inv1);
            float vb = o[nf][2 * p + 1] * ((p == 0) ? inv0 : inv1);
            *reinterpret_cast<unsigned*>(AO + (size_t)r * HID + h * HD + d) = packh2(va, vb);
        }
}

// ---------------- host launch ----------------
typedef CUresult (*EncodeFn)(
    CUtensorMap*, CUtensorMapDataType, cuuint32_t, void*,
    const cuuint64_t*, const cuuint64_t*, const cuuint32_t*, const cuuint32_t*,
    CUtensorMapInterleave, CUtensorMapSwizzle, CUtensorMapL2promotion, CUtensorMapFloatOOBfill);

static void make_map2(EncodeFn fn, CUtensorMap* map, void* base, uint64_t cols, uint64_t rows,
                      uint32_t boxX, uint32_t boxY) {
    cuuint64_t dims[2] = {(cuuint64_t)cols, (cuuint64_t)rows};
    cuuint64_t strides[1] = {(cuuint64_t)cols * 2};
    cuuint32_t box[2] = {boxX, boxY};
    cuuint32_t estr[2] = {1, 1};
    fn(map, CU_TENSOR_MAP_DATA_TYPE_FLOAT16, 2, base, dims, strides, box, estr,
       CU_TENSOR_MAP_INTERLEAVE_NONE, CU_TENSOR_MAP_SWIZZLE_128B,
       CU_TENSOR_MAP_L2_PROMOTION_L2_128B, CU_TENSOR_MAP_FLOAT_OOB_FILL_NONE);
}

extern "C" void kernel_launch(void* const* d_in, const int* in_sizes, int n_in,
                              void* d_out, int out_size) {
    (void)in_sizes; (void)n_in; (void)out_size;
    const float* hidden = (const float*)d_in[0];
    const int*   wq   = (const int*)d_in[2];
    const float* wq_s = (const float*)d_in[3];
    const float* bq   = (const float*)d_in[4];
    const int*   wk   = (const int*)d_in[5];
    const float* wk_s = (const float*)d_in[6];
    const float* bk   = (const float*)d_in[7];
    const int*   wv   = (const int*)d_in[8];
    const float* wv_s = (const float*)d_in[9];
    const int*   wo   = (const int*)d_in[10];
    const float* wo_s = (const float*)d_in[11];
    float* out = (float*)d_out;

    h16 *Xh, *Wqkv, *Wo, *Q, *K, *V, *AO;
    float *Sq, *Bq;
    cudaGetSymbolAddress((void**)&Xh,   g_Xh);
    cudaGetSymbolAddress((void**)&Wqkv, g_Wqkv);
    cudaGetSymbolAddress((void**)&Wo,   g_Wo);
    cudaGetSymbolAddress((void**)&Sq,   g_Sqkv);
    cudaGetSymbolAddress((void**)&Bq,   g_Bqkv);
    cudaGetSymbolAddress((void**)&Q,    g_Q);
    cudaGetSymbolAddress((void**)&K,    g_K);
    cudaGetSymbolAddress((void**)&V,    g_V);
    cudaGetSymbolAddress((void**)&AO,   g_AO);

    EncodeFn enc = nullptr;
    {
        void* fnp = nullptr;
        cudaDriverEntryPointQueryResult qres;
        cudaGetDriverEntryPoint("cuTensorMapEncodeTiled", &fnp, cudaEnableDefault, &qres);
        enc = (EncodeFn)fnp;
    }
    CUtensorMap mapX, mapWqkv, mapAO, mapWo, mapK, mapV;
    make_map2(enc, &mapX,    Xh,   HID, TT,   64, 128);
    make_map2(enc, &mapWqkv, Wqkv, HID, NQKV, 64, 128);
    make_map2(enc, &mapAO,   AO,   HID, TT,   64, 128);
    make_map2(enc, &mapWo,   Wo,   HID, HID,  64, 128);
    make_map2(enc, &mapK,    K,    HD, (uint64_t)BSZ * NKV * SEQ, 64, 64);
    make_map2(enc, &mapV,    V,    HD, (uint64_t)BSZ * NKV * SEQ, 64, 64);

    cudaFuncSetAttribute(gemm_tma, cudaFuncAttributeMaxDynamicSharedMemorySize, GEMM_SMEM);
    cudaFuncSetAttribute(attn_kernel, cudaFuncAttributeMaxDynamicSharedMemorySize, ATTN_SMEM);

    // ONE fused conversion kernel
    convert_all_kernel<<<(U_TOT + 255) / 256, 256>>>(
        wq, wk, wv, wo, hidden, wq_s, bq, wk_s, bk, wv_s, Wqkv, Wo, Xh, Sq, Bq);

    // fused QKV projection (single GEMM over N=6144)
    gemm_tma<<<dim3(NQKV / 128, TT / 128), 256, GEMM_SMEM>>>(
        mapX, mapWqkv, Sq, Bq, NQKV, 1, nullptr, Q, K, V);

    // causal GQA flash attention (TMA KV pipeline) -> fp16 AO (token-major)
    attn_kernel<<<dim3(SEQ / 128, NH, BSZ), 256, ATTN_SMEM>>>(mapK, mapV, Q, AO);

    // output projection -> fp32 d_out
    gemm_tma<<<dim3(HID / 128, TT / 128), 256, GEMM_SMEM>>>(
        mapAO, mapWo, wo_s, nullptr, HID, 0, out, nullptr, nullptr, nullptr);
}